// round 15
// baseline (speedup 1.0000x reference)
#include <cuda_runtime.h>
#include <cuda_fp16.h>
#include <math.h>
#include <cstdint>

// ---------------- problem constants ----------------
#define M_TOK   16384            // 4 * 4096 tokens
#define DIMX    1024
#define HID     2048
#define NEXP    8
#define TOPK    2
#define RROWS   (M_TOK * TOPK)   // 32768 (token, slot) rows

#define WSCALE   1024.0f         // weight pre-scale (exact power of 2)
#define IWSCALE  (1.0f / 1024.0f)

// ---------------- device scratch (static .bss; no allocations) ----------------
__device__ __half g_xn[(size_t)M_TOK * DIMX];             // fp16 normalized activations
__device__ __half g_h[(size_t)(RROWS + 128) * HID];       // fp16 SwiGLU output, +pad rows
__device__ float  g_down[(size_t)RROWS * DIMX];           // down-proj per (token,slot), unweighted
__device__ __half g_wup[(size_t)NEXP * 2 * HID * DIMX];   // fp16 w_up * 1024
__device__ __half g_wdn[(size_t)NEXP * DIMX * HID];       // fp16 w_down * 1024
__device__ int    g_cnt[NEXP];
__device__ int    g_list[NEXP * M_TOK];                   // per-expert token lists
__device__ int    g_se[RROWS];
__device__ int    g_sj[RROWS];
__device__ float  g_sw[RROWS];

// ---------------- helpers ----------------
__device__ __forceinline__ unsigned sptr(const void* p) {
    return (unsigned)__cvta_generic_to_shared(p);
}
__device__ __forceinline__ void cp16(unsigned s, const void* g) {
    asm volatile("cp.async.cg.shared.global [%0], [%1], 16;" :: "r"(s), "l"(g));
}
// arrive on mbarrier when ALL prior cp.async of this thread have completed.
// .noinc is LOAD-BEARING: init count already includes this arrival; without it
// the pending count is incremented at issue (net zero) -> deadlock (round 12).
__device__ __forceinline__ void cp_arrive(uint32_t mbar) {
    asm volatile("cp.async.mbarrier.arrive.noinc.shared::cta.b64 [%0];" :: "r"(mbar) : "memory");
}
__device__ __forceinline__ void mbar_init(uint32_t a, uint32_t cnt) {
    asm volatile("mbarrier.init.shared.b64 [%0], %1;" :: "r"(a), "r"(cnt) : "memory");
}
__device__ __forceinline__ void mbar_arrive(uint32_t a) {
    asm volatile("mbarrier.arrive.shared.b64 _, [%0];" :: "r"(a) : "memory");
}
__device__ __forceinline__ void mbar_wait(uint32_t a, uint32_t par) {
    uint32_t done;
    asm volatile(
        "{\n\t.reg .pred p;\n\t"
        "mbarrier.try_wait.parity.acquire.cta.shared::cta.b64 p, [%1], %2;\n\t"
        "selp.b32 %0, 1, 0, p;\n\t}"
        : "=r"(done) : "r"(a), "r"(par) : "memory");
    if (!done) {
        asm volatile(
            "{\n\t.reg .pred P1;\n\t"
            "WL%=:\n\t"
            "mbarrier.try_wait.parity.acquire.cta.shared::cta.b64 P1, [%0], %1, 0x989680;\n\t"
            "@P1 bra.uni WD%=;\n\t"
            "bra.uni WL%=;\n\t"
            "WD%=:\n\t}"
            :: "r"(a), "r"(par) : "memory");
    }
}

// fp16 MMA, f32 accumulate: D(16x8) += A(16x16) * B(16x8)
__device__ __forceinline__ void mma_f16(float* c, const uint32_t* a, uint32_t b0, uint32_t b1) {
    asm volatile(
        "mma.sync.aligned.m16n8k16.row.col.f32.f16.f16.f32 "
        "{%0,%1,%2,%3}, {%4,%5,%6,%7}, {%8,%9}, {%0,%1,%2,%3};"
        : "+f"(c[0]), "+f"(c[1]), "+f"(c[2]), "+f"(c[3])
        : "r"(a[0]), "r"(a[1]), "r"(a[2]), "r"(a[3]), "r"(b0), "r"(b1));
}
__device__ __forceinline__ void ldsm_x4(uint32_t* r, uint32_t addr) {
    asm volatile("ldmatrix.sync.aligned.m8n8.x4.shared.b16 {%0,%1,%2,%3}, [%4];"
        : "=r"(r[0]), "=r"(r[1]), "=r"(r[2]), "=r"(r[3]) : "r"(addr));
}
__device__ __forceinline__ void ldsm_x2(uint32_t& r0, uint32_t& r1, uint32_t addr) {
    asm volatile("ldmatrix.sync.aligned.m8n8.x2.shared.b16 {%0,%1}, [%2];"
        : "=r"(r0), "=r"(r1) : "r"(addr));
}

// ---------------- GEMM geometry ----------------
// block tile 128(M) x 128(N), BK=64, 256 threads = 8 warps as 2(M) x 4(N), warp tile 64x32
// 3 stages + mbarrier producer/consumer pipeline (no __syncthreads in mainloop)
// 111KB smem, <=128 regs -> 2 CTAs/SM; waits per FLOP halved vs BK=32
#define BK      64
#define BM      128
#define BN      128
#define ASTRH   72                        // smem halves per 64-half row (144B padded): LDSM phases conflict-free (4r mod 32)
#define STG_H   ((BM + BN) * ASTRH)       // 18432 halves per stage
#define STG_B   (STG_H * 2)               // 36864 bytes
#define STAGES  3
#define BAR_OFF (STAGES * STG_B)          // byte offset of mbarriers: 110592
#define TOKS_OFF (BAR_OFF + 64)           // byte offset of toks
#define SMEM_TOT (TOKS_OFF + 512)         // 111168 bytes

// ---------------- kernel 1: zero counters ----------------
__global__ void k_zero() {
    if (threadIdx.x < NEXP) g_cnt[threadIdx.x] = 0;
}

// ---------------- kernel 2: convert weights to fp16 * 1024 ----------------
__global__ void k_prep(const float* __restrict__ wu, const float* __restrict__ wd) {
    int i = blockIdx.x * blockDim.x + threadIdx.x;
    int stride = gridDim.x * blockDim.x;
    const int NU = NEXP * 2 * HID * DIMX / 4;
    const int ND = NEXP * DIMX * HID / 4;
    const float4* u4 = (const float4*)wu;
    const float4* d4 = (const float4*)wd;
    for (int j = i; j < NU; j += stride) {
        float4 v = u4[j];
        __half2* o = (__half2*)(g_wup + (size_t)j * 4);
        o[0] = __floats2half2_rn(v.x * WSCALE, v.y * WSCALE);
        o[1] = __floats2half2_rn(v.z * WSCALE, v.w * WSCALE);
    }
    for (int j = i; j < ND; j += stride) {
        float4 v = d4[j];
        __half2* o = (__half2*)(g_wdn + (size_t)j * 4);
        o[0] = __floats2half2_rn(v.x * WSCALE, v.y * WSCALE);
        o[1] = __floats2half2_rn(v.z * WSCALE, v.w * WSCALE);
    }
}

// ---------------- kernel 3: RMSNorm + router + top2 + softmax + list build ----------------
__global__ void k_rms_router(const float* __restrict__ x,
                             const float* __restrict__ scale,
                             const float* __restrict__ wr) {
    __shared__ float sx[DIMX];
    __shared__ float sred[8];
    __shared__ float sscore[8];
    int t = blockIdx.x, tid = threadIdx.x;

    const float4* xr = (const float4*)(x + (size_t)t * DIMX);
    float4 v = xr[tid];
    float ss = v.x * v.x + v.y * v.y + v.z * v.z + v.w * v.w;
    #pragma unroll
    for (int o = 16; o; o >>= 1) ss += __shfl_xor_sync(0xffffffffu, ss, o);
    if ((tid & 31) == 0) sred[tid >> 5] = ss;
    __syncthreads();
    if (tid == 0) {
        float a = 0.f;
        #pragma unroll
        for (int i = 0; i < 8; i++) a += sred[i];
        sred[0] = a;
    }
    __syncthreads();
    float ms = sred[0] * (1.0f / (float)DIMX);
    float rs = rsqrtf(ms + 1e-6f);
    float4 sc = ((const float4*)scale)[tid];
    float4 xn;
    xn.x = v.x * sc.x * rs; xn.y = v.y * sc.y * rs;
    xn.z = v.z * sc.z * rs; xn.w = v.w * sc.w * rs;
    ((float4*)sx)[tid] = xn;                       // full precision for router
    __half2* hp = (__half2*)(g_xn + (size_t)t * DIMX + 4 * tid);
    hp[0] = __floats2half2_rn(xn.x, xn.y);
    hp[1] = __floats2half2_rn(xn.z, xn.w);
    __syncthreads();

    int w = tid >> 5, lane = tid & 31;
    const float* wrow = wr + w * DIMX;
    float acc = 0.f;
    #pragma unroll 8
    for (int j = lane; j < DIMX; j += 32) acc += sx[j] * __ldg(wrow + j);
    #pragma unroll
    for (int o = 16; o; o >>= 1) acc += __shfl_xor_sync(0xffffffffu, acc, o);
    if (lane == 0) sscore[w] = acc;
    __syncthreads();

    if (tid == 0) {
        float s0 = -1e30f; int i0 = 0;
        #pragma unroll
        for (int i = 0; i < 8; i++) { float s = sscore[i]; if (s > s0) { s0 = s; i0 = i; } }
        float s1 = -1e30f; int i1 = 0;
        #pragma unroll
        for (int i = 0; i < 8; i++) { if (i == i0) continue; float s = sscore[i]; if (s > s1) { s1 = s; i1 = i; } }
        float e1 = __expf(s1 - s0);
        float w0 = 1.f / (1.f + e1);
        float w1 = e1 * w0;
        int p0 = atomicAdd(&g_cnt[i0], 1);
        g_list[i0 * M_TOK + p0] = t;
        g_se[2 * t] = i0; g_sj[2 * t] = p0; g_sw[2 * t] = w0;
        int p1 = atomicAdd(&g_cnt[i1], 1);
        g_list[i1 * M_TOK + p1] = t;
        g_se[2 * t + 1] = i1; g_sj[2 * t + 1] = p1; g_sw[2 * t + 1] = w1;
    }
}

// ---------------- scheduling: blockIdx.y -> (expert, row-tile) ----------------
struct Sched { int e, rt, valid, pbase; bool ok; };
__device__ __forceinline__ Sched sched_rowtile(int tile) {
    Sched s; s.ok = false;
    int off = 0;
    for (int e = 0; e < NEXP; e++) {
        int c = g_cnt[e];
        int nt = (c + 127) >> 7;
        if (tile < nt) {
            s.e = e; s.rt = tile;
            s.valid = min(128, c - tile * 128);
            s.pbase = off + tile * 128;
            s.ok = true;
            return s;
        }
        tile -= nt; off += c;
    }
    return s;
}

// ---------------- kernel 4: up GEMM (fp16 mma; block covers 64 u + 64 gate cols) ----------------
#define KTU (DIMX / BK)   // 16

__global__ void __launch_bounds__(256, 2) k_up() {
    extern __shared__ __half smem[];
    uint32_t sb = sptr(smem);
    int tid = threadIdx.x, wid = tid >> 5, lane = tid & 31;
    int g = lane >> 2, tg = lane & 3;

    Sched sc = sched_rowtile(blockIdx.y);
    if (!sc.ok) return;
    int c0 = blockIdx.x * 64;           // u/gate HID column base
    int lbase = sc.e * M_TOK + sc.rt * 128;

    uint32_t fullb = sb + BAR_OFF;       // 3 x 8B
    uint32_t emptyb = sb + BAR_OFF + 32; // 3 x 8B
    if (tid == 0) {
        #pragma unroll
        for (int s = 0; s < STAGES; s++) {
            mbar_init(fullb + 8 * s, 256);
            mbar_init(emptyb + 8 * s, 8);
        }
    }
    int* toks = (int*)((char*)smem + TOKS_OFF);
    if (tid < 128)
        toks[tid] = (tid < sc.valid) ? g_list[lbase + tid] : g_list[lbase];
    __syncthreads();

    // A loader: thread t -> row t>>1, 32-half group t&1 (four cp16)
    int arow = tid >> 1;
    const __half* a_src = g_xn + (size_t)toks[arow] * DIMX + (tid & 1) * 32;
    uint32_t a_dst = sb + (arow * ASTRH + (tid & 1) * 32) * 2;
    // B loader: block row br = w8*32 + j: j<16 -> u col c0+w8*16+j ; j>=16 -> gate
    int br = tid >> 1, w8 = br >> 5, j = br & 31;
    int bhid = c0 + w8 * 16 + (j & 15);
    int brow = (j < 16) ? bhid : (HID + bhid);
    const __half* WU = g_wup + (size_t)sc.e * 2 * HID * DIMX;
    const __half* b_src = WU + (size_t)brow * DIMX + (tid & 1) * 32;
    uint32_t b_dst = sb + ((BM + br) * ASTRH + (tid & 1) * 32) * 2;

    auto load_tile = [&](int ti, int st) {
        uint32_t so = (uint32_t)st * STG_B;
        const __half* ap = a_src + ti * BK;
        const __half* bp = b_src + ti * BK;
        cp16(a_dst + so,      ap);
        cp16(a_dst + so + 16, ap + 8);
        cp16(a_dst + so + 32, ap + 16);
        cp16(a_dst + so + 48, ap + 24);
        cp16(b_dst + so,      bp);
        cp16(b_dst + so + 16, bp + 8);
        cp16(b_dst + so + 32, bp + 16);
        cp16(b_dst + so + 48, bp + 24);
    };

    // prologue: produce tiles 0..1 (stages 0..1)
    #pragma unroll
    for (int ti = 0; ti < 2; ti++) {
        load_tile(ti, ti);
        cp_arrive(fullb + 8 * ti);
    }

    float acc[4][4][4] = {};
    int wm = (wid >> 2) * 64, wq = wid & 3;
    uint32_t a_off = ((wm + (lane & 15)) * ASTRH + (lane >> 4) * 8) * 2;
    uint32_t b_off = ((BM + wq * 32 + (lane & 7)) * ASTRH + ((lane >> 3) & 1) * 8) * 2;

    for (int kt = 0; kt < KTU; kt++) {
        int s = kt % 3;
        mbar_wait(fullb + 8 * s, (kt / 3) & 1);
        uint32_t Sb = sb + (uint32_t)s * STG_B;
        #pragma unroll
        for (int ks = 0; ks < 4; ks++) {
            uint32_t a[4][4];
            #pragma unroll
            for (int mt = 0; mt < 4; mt++)
                ldsm_x4(a[mt], Sb + a_off + mt * (16 * ASTRH * 2) + ks * 32);
            #pragma unroll
            for (int nt = 0; nt < 4; nt++) {
                uint32_t b0, b1;
                ldsm_x2(b0, b1, Sb + b_off + nt * (8 * ASTRH * 2) + ks * 32);
                #pragma unroll
                for (int mt = 0; mt < 4; mt++)
                    mma_f16(acc[mt][nt], a[mt], b0, b1);
            }
        }
        if (lane == 0) mbar_arrive(emptyb + 8 * s);
        int ti = kt + 2;
        if (ti < KTU) {
            int s2 = ti % 3;
            if (ti >= 3) mbar_wait(emptyb + 8 * s2, ((ti / 3) - 1) & 1);
            load_tile(ti, s2);
            cp_arrive(fullb + 8 * s2);
        }
    }

    // SwiGLU: warp covers HID cols [c0+wq*16, +16); nt 0..1 = u, nt 2..3 = gate (same cols)
    int ch0 = c0 + wq * 16;
    #pragma unroll
    for (int mt = 0; mt < 4; mt++) {
        #pragma unroll
        for (int hf = 0; hf < 2; hf++) {
            int r = wm + mt * 16 + g + hf * 8;
            if (r < sc.valid) {
                __half* orow = g_h + (size_t)(sc.pbase + r) * HID;
                #pragma unroll
                for (int nt = 0; nt < 2; nt++) {
                    int ch = ch0 + nt * 8 + 2 * tg;
                    float u0 = acc[mt][nt][hf * 2]     * IWSCALE;
                    float u1 = acc[mt][nt][hf * 2 + 1] * IWSCALE;
                    float q0 = acc[mt][nt + 2][hf * 2]     * IWSCALE;
                    float q1 = acc[mt][nt + 2][hf * 2 + 1] * IWSCALE;
                    float h0 = u0 * (q0 / (1.f + __expf(-q0)));
                    float h1 = u1 * (q1 / (1.f + __expf(-q1)));
                    *(__half2*)(orow + ch) = __floats2half2_rn(h0, h1);
                }
            }
        }
    }
}

// ---------------- kernel 5: down GEMM (fp16 mma, 128x128 block, K=2048) ----------------
#define KTD (HID / BK)    // 32

__global__ void __launch_bounds__(256, 2) k_down() {
    extern __shared__ __half smem[];
    uint32_t sb = sptr(smem);
    int tid = threadIdx.x, wid = tid >> 5, lane = tid & 31;
    int g = lane >> 2, tg = lane & 3;

    Sched sc = sched_rowtile(blockIdx.y);
    if (!sc.ok) return;
    int n0 = blockIdx.x * BN;

    uint32_t fullb = sb + BAR_OFF;
    uint32_t emptyb = sb + BAR_OFF + 32;
    if (tid == 0) {
        #pragma unroll
        for (int s = 0; s < STAGES; s++) {
            mbar_init(fullb + 8 * s, 256);
            mbar_init(emptyb + 8 * s, 8);
        }
    }
    __syncthreads();

    int arow = tid >> 1;
    const __half* a_src = g_h + (size_t)(sc.pbase + arow) * HID + (tid & 1) * 32;  // pad rows cover overrun
    uint32_t a_dst = sb + (arow * ASTRH + (tid & 1) * 32) * 2;
    const __half* WD = g_wdn + (size_t)sc.e * DIMX * HID;
    const __half* b_src = WD + (size_t)(n0 + arow) * HID + (tid & 1) * 32;
    uint32_t b_dst = sb + ((BM + arow) * ASTRH + (tid & 1) * 32) * 2;

    auto load_tile = [&](int ti, int st) {
        uint32_t so = (uint32_t)st * STG_B;
        const __half* ap = a_src + ti * BK;
        const __half* bp = b_src + ti * BK;
        cp16(a_dst + so,      ap);
        cp16(a_dst + so + 16, ap + 8);
        cp16(a_dst + so + 32, ap + 16);
        cp16(a_dst + so + 48, ap + 24);
        cp16(b_dst + so,      bp);
        cp16(b_dst + so + 16, bp + 8);
        cp16(b_dst + so + 32, bp + 16);
        cp16(b_dst + so + 48, bp + 24);
    };

    #pragma unroll
    for (int ti = 0; ti < 2; ti++) {
        load_tile(ti, ti);
        cp_arrive(fullb + 8 * ti);
    }

    float acc[4][4][4] = {};
    int wm = (wid >> 2) * 64, wq = wid & 3;
    uint32_t a_off = ((wm + (lane & 15)) * ASTRH + (lane >> 4) * 8) * 2;
    uint32_t b_off = ((BM + wq * 32 + (lane & 7)) * ASTRH + ((lane >> 3) & 1) * 8) * 2;

    for (int kt = 0; kt < KTD; kt++) {
        int s = kt % 3;
        mbar_wait(fullb + 8 * s, (kt / 3) & 1);
        uint32_t Sb = sb + (uint32_t)s * STG_B;
        #pragma unroll
        for (int ks = 0; ks < 4; ks++) {
            uint32_t a[4][4];
            #pragma unroll
            for (int mt = 0; mt < 4; mt++)
                ldsm_x4(a[mt], Sb + a_off + mt * (16 * ASTRH * 2) + ks * 32);
            #pragma unroll
            for (int nt = 0; nt < 4; nt++) {
                uint32_t b0, b1;
                ldsm_x2(b0, b1, Sb + b_off + nt * (8 * ASTRH * 2) + ks * 32);
                #pragma unroll
                for (int mt = 0; mt < 4; mt++)
                    mma_f16(acc[mt][nt], a[mt], b0, b1);
            }
        }
        if (lane == 0) mbar_arrive(emptyb + 8 * s);
        int ti = kt + 2;
        if (ti < KTD) {
            int s2 = ti % 3;
            if (ti >= 3) mbar_wait(emptyb + 8 * s2, ((ti / 3) - 1) & 1);
            load_tile(ti, s2);
            cp_arrive(fullb + 8 * s2);
        }
    }

    #pragma unroll
    for (int mt = 0; mt < 4; mt++) {
        #pragma unroll
        for (int hf = 0; hf < 2; hf++) {
            int r = wm + mt * 16 + g + hf * 8;
            if (r < sc.valid) {
                float* orow = g_down + (size_t)(sc.pbase + r) * DIMX + n0;
                #pragma unroll
                for (int nt = 0; nt < 4; nt++) {
                    int cc = wq * 32 + nt * 8 + 2 * tg;
                    float2 v;
                    v.x = acc[mt][nt][hf * 2]     * IWSCALE;
                    v.y = acc[mt][nt][hf * 2 + 1] * IWSCALE;
                    *(float2*)(orow + cc) = v;
                }
            }
        }
    }
}

// ---------------- kernel 6: combine out = x + w0*down[p0] + w1*down[p1] ----------------
__global__ void k_combine(const float* __restrict__ x, float* __restrict__ out) {
    int t = blockIdx.x, tid = threadIdx.x;
    int e0 = g_se[2 * t], j0 = g_sj[2 * t];
    int e1 = g_se[2 * t + 1], j1 = g_sj[2 * t + 1];
    float w0 = g_sw[2 * t], w1 = g_sw[2 * t + 1];
    int off0 = 0, off1 = 0;
    #pragma unroll
    for (int i = 0; i < 8; i++) {
        int ci = __ldg(&g_cnt[i]);
        if (i < e0) off0 += ci;
        if (i < e1) off1 += ci;
    }
    int p0 = off0 + j0, p1 = off1 + j1;
    const float4* x4 = (const float4*)(x + (size_t)t * DIMX);
    const float4* d0 = (const float4*)(g_down + (size_t)p0 * DIMX);
    const float4* d1 = (const float4*)(g_down + (size_t)p1 * DIMX);
    float4 a = x4[tid], u = d0[tid], v = d1[tid];
    float4 o;
    o.x = a.x + w0 * u.x + w1 * v.x;
    o.y = a.y + w0 * u.y + w1 * v.y;
    o.z = a.z + w0 * u.z + w1 * v.z;
    o.w = a.w + w0 * u.w + w1 * v.w;
    ((float4*)(out + (size_t)t * DIMX))[tid] = o;
}

// ---------------- launch ----------------
extern "C" void kernel_launch(void* const* d_in, const int* in_sizes, int n_in,
                              void* d_out, int out_size) {
    const float* x     = (const float*)d_in[0];
    const float* scale = (const float*)d_in[1];
    const float* wr    = (const float*)d_in[2];
    const float* wu    = (const float*)d_in[3];
    const float* wd    = (const float*)d_in[4];
    float* out = (float*)d_out;

    cudaFuncSetAttribute(k_up,   cudaFuncAttributeMaxDynamicSharedMemorySize, SMEM_TOT);
    cudaFuncSetAttribute(k_down, cudaFuncAttributeMaxDynamicSharedMemorySize, SMEM_TOT);

    k_zero<<<1, 32>>>();
    k_prep<<<2048, 256>>>(wu, wd);
    k_rms_router<<<M_TOK, 256>>>(x, scale, wr);
    // grid: x = n-tile (fast: a wave shares A row-tile, keeps B in L2), y = row-tile (264 >= 263 worst case)
    k_up  <<<dim3(HID / 64, 264), 256, SMEM_TOT>>>();    // (32, 264)
    k_down<<<dim3(DIMX / BN, 264), 256, SMEM_TOT>>>();   // (8, 264)
    k_combine<<<M_TOK, 256>>>(x, out);
}

// round 16
// speedup vs baseline: 1.2353x; 1.2353x over previous
#include <cuda_runtime.h>
#include <cuda_fp16.h>
#include <math.h>
#include <cstdint>

// ---------------- problem constants ----------------
#define M_TOK   16384            // 4 * 4096 tokens
#define DIMX    1024
#define HID     2048
#define NEXP    8
#define TOPK    2
#define RROWS   (M_TOK * TOPK)   // 32768 (token, slot) rows

#define WSCALE   1024.0f         // weight pre-scale (exact power of 2)
#define IWSCALE  (1.0f / 1024.0f)

// ---------------- device scratch (static .bss; no allocations) ----------------
__device__ __half g_xn[(size_t)M_TOK * DIMX];             // fp16 normalized activations
__device__ __half g_h[(size_t)(RROWS + 128) * HID];       // fp16 SwiGLU output, +pad rows
__device__ __half g_down[(size_t)RROWS * DIMX];           // down-proj per (token,slot), fp16 unweighted
__device__ __half g_wup[(size_t)NEXP * 2 * HID * DIMX];   // fp16 w_up * 1024
__device__ __half g_wdn[(size_t)NEXP * DIMX * HID];       // fp16 w_down * 1024
__device__ int    g_cnt[NEXP];
__device__ int    g_list[NEXP * M_TOK];                   // per-expert token lists
__device__ int    g_se[RROWS];
__device__ int    g_sj[RROWS];
__device__ float  g_sw[RROWS];

// ---------------- helpers ----------------
__device__ __forceinline__ unsigned sptr(const void* p) {
    return (unsigned)__cvta_generic_to_shared(p);
}
__device__ __forceinline__ void cp16(unsigned s, const void* g) {
    asm volatile("cp.async.cg.shared.global [%0], [%1], 16;" :: "r"(s), "l"(g));
}
// arrive on mbarrier when ALL prior cp.async of this thread have completed.
// .noinc is LOAD-BEARING: init count already includes this arrival; without it
// the pending count is incremented at issue (net zero) -> deadlock (round 12).
__device__ __forceinline__ void cp_arrive(uint32_t mbar) {
    asm volatile("cp.async.mbarrier.arrive.noinc.shared::cta.b64 [%0];" :: "r"(mbar) : "memory");
}
__device__ __forceinline__ void mbar_init(uint32_t a, uint32_t cnt) {
    asm volatile("mbarrier.init.shared.b64 [%0], %1;" :: "r"(a), "r"(cnt) : "memory");
}
__device__ __forceinline__ void mbar_arrive(uint32_t a) {
    asm volatile("mbarrier.arrive.shared.b64 _, [%0];" :: "r"(a) : "memory");
}
__device__ __forceinline__ void mbar_wait(uint32_t a, uint32_t par) {
    uint32_t done;
    asm volatile(
        "{\n\t.reg .pred p;\n\t"
        "mbarrier.try_wait.parity.acquire.cta.shared::cta.b64 p, [%1], %2;\n\t"
        "selp.b32 %0, 1, 0, p;\n\t}"
        : "=r"(done) : "r"(a), "r"(par) : "memory");
    if (!done) {
        asm volatile(
            "{\n\t.reg .pred P1;\n\t"
            "WL%=:\n\t"
            "mbarrier.try_wait.parity.acquire.cta.shared::cta.b64 P1, [%0], %1, 0x989680;\n\t"
            "@P1 bra.uni WD%=;\n\t"
            "bra.uni WL%=;\n\t"
            "WD%=:\n\t}"
            :: "r"(a), "r"(par) : "memory");
    }
}

// fp16 MMA, f32 accumulate: D(16x8) += A(16x16) * B(16x8)
__device__ __forceinline__ void mma_f16(float* c, const uint32_t* a, uint32_t b0, uint32_t b1) {
    asm volatile(
        "mma.sync.aligned.m16n8k16.row.col.f32.f16.f16.f32 "
        "{%0,%1,%2,%3}, {%4,%5,%6,%7}, {%8,%9}, {%0,%1,%2,%3};"
        : "+f"(c[0]), "+f"(c[1]), "+f"(c[2]), "+f"(c[3])
        : "r"(a[0]), "r"(a[1]), "r"(a[2]), "r"(a[3]), "r"(b0), "r"(b1));
}
__device__ __forceinline__ void ldsm_x4(uint32_t* r, uint32_t addr) {
    asm volatile("ldmatrix.sync.aligned.m8n8.x4.shared.b16 {%0,%1,%2,%3}, [%4];"
        : "=r"(r[0]), "=r"(r[1]), "=r"(r[2]), "=r"(r[3]) : "r"(addr));
}
__device__ __forceinline__ void ldsm_x2(uint32_t& r0, uint32_t& r1, uint32_t addr) {
    asm volatile("ldmatrix.sync.aligned.m8n8.x2.shared.b16 {%0,%1}, [%2];"
        : "=r"(r0), "=r"(r1) : "r"(addr));
}

// ---------------- GEMM geometry (round-13 proven config) ----------------
// block tile 128(M) x 128(N), BK=32, 256 threads = 8 warps as 2(M) x 4(N), warp tile 64x32
// 4 stages + mbarrier producer/consumer pipeline (no __syncthreads in mainloop)
// ~82KB smem, <=128 regs -> 2 CTAs/SM (two independent pipeline domains per SM)
#define BK      32
#define BM      128
#define BN      128
#define ASTRH   40                        // smem halves per 32-half row (80B, padded): LDSM phases conflict-free
#define STG_H   ((BM + BN) * ASTRH)       // 10240 halves per stage
#define STG_B   (STG_H * 2)               // 20480 bytes
#define STAGES  4
#define BAR_OFF (STAGES * STG_B)          // byte offset of mbarriers: 81920
#define TOKS_OFF (BAR_OFF + 64)           // byte offset of toks
#define SMEM_TOT (TOKS_OFF + 512)         // 82496 bytes

// ---------------- kernel 1: convert weights to fp16 * 1024 (+ zero counters) ----------------
__global__ void k_prep(const float* __restrict__ wu, const float* __restrict__ wd) {
    if (blockIdx.x == 0 && threadIdx.x < NEXP) g_cnt[threadIdx.x] = 0;
    int i = blockIdx.x * blockDim.x + threadIdx.x;
    int stride = gridDim.x * blockDim.x;
    const int NU = NEXP * 2 * HID * DIMX / 4;
    const int ND = NEXP * DIMX * HID / 4;
    const float4* u4 = (const float4*)wu;
    const float4* d4 = (const float4*)wd;
    for (int j = i; j < NU; j += stride) {
        float4 v = u4[j];
        __half2* o = (__half2*)(g_wup + (size_t)j * 4);
        o[0] = __floats2half2_rn(v.x * WSCALE, v.y * WSCALE);
        o[1] = __floats2half2_rn(v.z * WSCALE, v.w * WSCALE);
    }
    for (int j = i; j < ND; j += stride) {
        float4 v = d4[j];
        __half2* o = (__half2*)(g_wdn + (size_t)j * 4);
        o[0] = __floats2half2_rn(v.x * WSCALE, v.y * WSCALE);
        o[1] = __floats2half2_rn(v.z * WSCALE, v.w * WSCALE);
    }
}

// ---------------- kernel 2: RMSNorm + router + top2 + softmax + list build ----------------
__global__ void k_rms_router(const float* __restrict__ x,
                             const float* __restrict__ scale,
                             const float* __restrict__ wr) {
    __shared__ float sx[DIMX];
    __shared__ float sred[8];
    __shared__ float sscore[8];
    int t = blockIdx.x, tid = threadIdx.x;

    const float4* xr = (const float4*)(x + (size_t)t * DIMX);
    float4 v = xr[tid];
    float ss = v.x * v.x + v.y * v.y + v.z * v.z + v.w * v.w;
    #pragma unroll
    for (int o = 16; o; o >>= 1) ss += __shfl_xor_sync(0xffffffffu, ss, o);
    if ((tid & 31) == 0) sred[tid >> 5] = ss;
    __syncthreads();
    if (tid == 0) {
        float a = 0.f;
        #pragma unroll
        for (int i = 0; i < 8; i++) a += sred[i];
        sred[0] = a;
    }
    __syncthreads();
    float ms = sred[0] * (1.0f / (float)DIMX);
    float rs = rsqrtf(ms + 1e-6f);
    float4 sc = ((const float4*)scale)[tid];
    float4 xn;
    xn.x = v.x * sc.x * rs; xn.y = v.y * sc.y * rs;
    xn.z = v.z * sc.z * rs; xn.w = v.w * sc.w * rs;
    ((float4*)sx)[tid] = xn;                       // full precision for router
    __half2* hp = (__half2*)(g_xn + (size_t)t * DIMX + 4 * tid);
    hp[0] = __floats2half2_rn(xn.x, xn.y);
    hp[1] = __floats2half2_rn(xn.z, xn.w);
    __syncthreads();

    int w = tid >> 5, lane = tid & 31;
    const float* wrow = wr + w * DIMX;
    float acc = 0.f;
    #pragma unroll 8
    for (int j = lane; j < DIMX; j += 32) acc += sx[j] * __ldg(wrow + j);
    #pragma unroll
    for (int o = 16; o; o >>= 1) acc += __shfl_xor_sync(0xffffffffu, acc, o);
    if (lane == 0) sscore[w] = acc;
    __syncthreads();

    if (tid == 0) {
        float s0 = -1e30f; int i0 = 0;
        #pragma unroll
        for (int i = 0; i < 8; i++) { float s = sscore[i]; if (s > s0) { s0 = s; i0 = i; } }
        float s1 = -1e30f; int i1 = 0;
        #pragma unroll
        for (int i = 0; i < 8; i++) { if (i == i0) continue; float s = sscore[i]; if (s > s1) { s1 = s; i1 = i; } }
        float e1 = __expf(s1 - s0);
        float w0 = 1.f / (1.f + e1);
        float w1 = e1 * w0;
        int p0 = atomicAdd(&g_cnt[i0], 1);
        g_list[i0 * M_TOK + p0] = t;
        g_se[2 * t] = i0; g_sj[2 * t] = p0; g_sw[2 * t] = w0;
        int p1 = atomicAdd(&g_cnt[i1], 1);
        g_list[i1 * M_TOK + p1] = t;
        g_se[2 * t + 1] = i1; g_sj[2 * t + 1] = p1; g_sw[2 * t + 1] = w1;
    }
}

// ---------------- scheduling: blockIdx.y -> (expert, row-tile) ----------------
struct Sched { int e, rt, valid, pbase; bool ok; };
__device__ __forceinline__ Sched sched_rowtile(int tile) {
    Sched s; s.ok = false;
    int off = 0;
    for (int e = 0; e < NEXP; e++) {
        int c = g_cnt[e];
        int nt = (c + 127) >> 7;
        if (tile < nt) {
            s.e = e; s.rt = tile;
            s.valid = min(128, c - tile * 128);
            s.pbase = off + tile * 128;
            s.ok = true;
            return s;
        }
        tile -= nt; off += c;
    }
    return s;
}

// ---------------- kernel 3: up GEMM (fp16 mma; block covers 64 u + 64 gate cols) ----------------
#define KTU (DIMX / BK)   // 32

__global__ void __launch_bounds__(256, 2) k_up() {
    extern __shared__ __half smem[];
    uint32_t sb = sptr(smem);
    int tid = threadIdx.x, wid = tid >> 5, lane = tid & 31;
    int g = lane >> 2, tg = lane & 3;

    Sched sc = sched_rowtile(blockIdx.y);
    if (!sc.ok) return;
    int c0 = blockIdx.x * 64;           // u/gate HID column base
    int lbase = sc.e * M_TOK + sc.rt * 128;

    uint32_t fullb = sb + BAR_OFF;       // 4 x 8B
    uint32_t emptyb = sb + BAR_OFF + 32; // 4 x 8B
    if (tid == 0) {
        #pragma unroll
        for (int s = 0; s < STAGES; s++) {
            mbar_init(fullb + 8 * s, 256);
            mbar_init(emptyb + 8 * s, 8);
        }
    }
    int* toks = (int*)((char*)smem + TOKS_OFF);
    if (tid < 128)
        toks[tid] = (tid < sc.valid) ? g_list[lbase + tid] : g_list[lbase];
    __syncthreads();

    // A loader: thread t -> row t>>1, 16-half group t&1 (two cp16)
    int arow = tid >> 1;
    const __half* a_src = g_xn + (size_t)toks[arow] * DIMX + (tid & 1) * 16;
    uint32_t a_dst = sb + (arow * ASTRH + (tid & 1) * 16) * 2;
    // B loader: block row br = w8*32 + j: j<16 -> u col c0+w8*16+j ; j>=16 -> gate
    int br = tid >> 1, w8 = br >> 5, j = br & 31;
    int bhid = c0 + w8 * 16 + (j & 15);
    int brow = (j < 16) ? bhid : (HID + bhid);
    const __half* WU = g_wup + (size_t)sc.e * 2 * HID * DIMX;
    const __half* b_src = WU + (size_t)brow * DIMX + (tid & 1) * 16;
    uint32_t b_dst = sb + ((BM + br) * ASTRH + (tid & 1) * 16) * 2;

    auto load_tile = [&](int ti, int st) {
        uint32_t so = (uint32_t)st * STG_B;
        const __half* ap = a_src + ti * BK;
        const __half* bp = b_src + ti * BK;
        cp16(a_dst + so, ap);
        cp16(a_dst + so + 16, ap + 8);
        cp16(b_dst + so, bp);
        cp16(b_dst + so + 16, bp + 8);
    };

    // prologue: produce tiles 0..2 (stages 0..2)
    #pragma unroll
    for (int ti = 0; ti < 3; ti++) {
        load_tile(ti, ti);
        cp_arrive(fullb + 8 * ti);
    }

    float acc[4][4][4] = {};
    int wm = (wid >> 2) * 64, wq = wid & 3;
    uint32_t a_off = ((wm + (lane & 15)) * ASTRH + (lane >> 4) * 8) * 2;
    uint32_t b_off = ((BM + wq * 32 + (lane & 7)) * ASTRH + ((lane >> 3) & 1) * 8) * 2;

    for (int kt = 0; kt < KTU; kt++) {
        int s = kt & 3;
        mbar_wait(fullb + 8 * s, (kt >> 2) & 1);
        uint32_t Sb = sb + (uint32_t)s * STG_B;
        #pragma unroll
        for (int ks = 0; ks < 2; ks++) {
            uint32_t a[4][4];
            #pragma unroll
            for (int mt = 0; mt < 4; mt++)
                ldsm_x4(a[mt], Sb + a_off + mt * (16 * ASTRH * 2) + ks * 32);
            #pragma unroll
            for (int nt = 0; nt < 4; nt++) {
                uint32_t b0, b1;
                ldsm_x2(b0, b1, Sb + b_off + nt * (8 * ASTRH * 2) + ks * 32);
                #pragma unroll
                for (int mt = 0; mt < 4; mt++)
                    mma_f16(acc[mt][nt], a[mt], b0, b1);
            }
        }
        if (lane == 0) mbar_arrive(emptyb + 8 * s);
        int ti = kt + 3;
        if (ti < KTU) {
            int s2 = ti & 3;
            if (ti >= 4) mbar_wait(emptyb + 8 * s2, ((ti >> 2) - 1) & 1);
            load_tile(ti, s2);
            cp_arrive(fullb + 8 * s2);
        }
    }

    // SwiGLU: warp covers HID cols [c0+wq*16, +16); nt 0..1 = u, nt 2..3 = gate (same cols)
    int ch0 = c0 + wq * 16;
    #pragma unroll
    for (int mt = 0; mt < 4; mt++) {
        #pragma unroll
        for (int hf = 0; hf < 2; hf++) {
            int r = wm + mt * 16 + g + hf * 8;
            if (r < sc.valid) {
                __half* orow = g_h + (size_t)(sc.pbase + r) * HID;
                #pragma unroll
                for (int nt = 0; nt < 2; nt++) {
                    int ch = ch0 + nt * 8 + 2 * tg;
                    float u0 = acc[mt][nt][hf * 2]     * IWSCALE;
                    float u1 = acc[mt][nt][hf * 2 + 1] * IWSCALE;
                    float q0 = acc[mt][nt + 2][hf * 2]     * IWSCALE;
                    float q1 = acc[mt][nt + 2][hf * 2 + 1] * IWSCALE;
                    float h0 = u0 * (q0 / (1.f + __expf(-q0)));
                    float h1 = u1 * (q1 / (1.f + __expf(-q1)));
                    *(__half2*)(orow + ch) = __floats2half2_rn(h0, h1);
                }
            }
        }
    }
}

// ---------------- kernel 4: down GEMM (fp16 mma, 128x128 block, K=2048) ----------------
#define KTD (HID / BK)    // 64

__global__ void __launch_bounds__(256, 2) k_down() {
    extern __shared__ __half smem[];
    uint32_t sb = sptr(smem);
    int tid = threadIdx.x, wid = tid >> 5, lane = tid & 31;
    int g = lane >> 2, tg = lane & 3;

    Sched sc = sched_rowtile(blockIdx.y);
    if (!sc.ok) return;
    int n0 = blockIdx.x * BN;

    uint32_t fullb = sb + BAR_OFF;
    uint32_t emptyb = sb + BAR_OFF + 32;
    if (tid == 0) {
        #pragma unroll
        for (int s = 0; s < STAGES; s++) {
            mbar_init(fullb + 8 * s, 256);
            mbar_init(emptyb + 8 * s, 8);
        }
    }
    __syncthreads();

    int arow = tid >> 1;
    const __half* a_src = g_h + (size_t)(sc.pbase + arow) * HID + (tid & 1) * 16;  // pad rows cover overrun
    uint32_t a_dst = sb + (arow * ASTRH + (tid & 1) * 16) * 2;
    const __half* WD = g_wdn + (size_t)sc.e * DIMX * HID;
    const __half* b_src = WD + (size_t)(n0 + arow) * HID + (tid & 1) * 16;
    uint32_t b_dst = sb + ((BM + arow) * ASTRH + (tid & 1) * 16) * 2;

    auto load_tile = [&](int ti, int st) {
        uint32_t so = (uint32_t)st * STG_B;
        const __half* ap = a_src + ti * BK;
        const __half* bp = b_src + ti * BK;
        cp16(a_dst + so, ap);
        cp16(a_dst + so + 16, ap + 8);
        cp16(b_dst + so, bp);
        cp16(b_dst + so + 16, bp + 8);
    };

    #pragma unroll
    for (int ti = 0; ti < 3; ti++) {
        load_tile(ti, ti);
        cp_arrive(fullb + 8 * ti);
    }

    float acc[4][4][4] = {};
    int wm = (wid >> 2) * 64, wq = wid & 3;
    uint32_t a_off = ((wm + (lane & 15)) * ASTRH + (lane >> 4) * 8) * 2;
    uint32_t b_off = ((BM + wq * 32 + (lane & 7)) * ASTRH + ((lane >> 3) & 1) * 8) * 2;

    for (int kt = 0; kt < KTD; kt++) {
        int s = kt & 3;
        mbar_wait(fullb + 8 * s, (kt >> 2) & 1);
        uint32_t Sb = sb + (uint32_t)s * STG_B;
        #pragma unroll
        for (int ks = 0; ks < 2; ks++) {
            uint32_t a[4][4];
            #pragma unroll
            for (int mt = 0; mt < 4; mt++)
                ldsm_x4(a[mt], Sb + a_off + mt * (16 * ASTRH * 2) + ks * 32);
            #pragma unroll
            for (int nt = 0; nt < 4; nt++) {
                uint32_t b0, b1;
                ldsm_x2(b0, b1, Sb + b_off + nt * (8 * ASTRH * 2) + ks * 32);
                #pragma unroll
                for (int mt = 0; mt < 4; mt++)
                    mma_f16(acc[mt][nt], a[mt], b0, b1);
            }
        }
        if (lane == 0) mbar_arrive(emptyb + 8 * s);
        int ti = kt + 3;
        if (ti < KTD) {
            int s2 = ti & 3;
            if (ti >= 4) mbar_wait(emptyb + 8 * s2, ((ti >> 2) - 1) & 1);
            load_tile(ti, s2);
            cp_arrive(fullb + 8 * s2);
        }
    }

    #pragma unroll
    for (int mt = 0; mt < 4; mt++) {
        #pragma unroll
        for (int hf = 0; hf < 2; hf++) {
            int r = wm + mt * 16 + g + hf * 8;
            if (r < sc.valid) {
                __half* orow = g_down + (size_t)(sc.pbase + r) * DIMX + n0;
                #pragma unroll
                for (int nt = 0; nt < 4; nt++) {
                    int cc = wq * 32 + nt * 8 + 2 * tg;
                    float vx = acc[mt][nt][hf * 2]     * IWSCALE;
                    float vy = acc[mt][nt][hf * 2 + 1] * IWSCALE;
                    *(__half2*)(orow + cc) = __floats2half2_rn(vx, vy);
                }
            }
        }
    }
}

// ---------------- kernel 5: combine out = x + w0*down[p0] + w1*down[p1] ----------------
__global__ void k_combine(const float* __restrict__ x, float* __restrict__ out) {
    int t = blockIdx.x, tid = threadIdx.x;
    int e0 = g_se[2 * t], j0 = g_sj[2 * t];
    int e1 = g_se[2 * t + 1], j1 = g_sj[2 * t + 1];
    float w0 = g_sw[2 * t], w1 = g_sw[2 * t + 1];
    int off0 = 0, off1 = 0;
    #pragma unroll
    for (int i = 0; i < 8; i++) {
        int ci = __ldg(&g_cnt[i]);
        if (i < e0) off0 += ci;
        if (i < e1) off1 += ci;
    }
    int p0 = off0 + j0, p1 = off1 + j1;
    const float4* x4 = (const float4*)(x + (size_t)t * DIMX);
    const __half2* d0 = (const __half2*)(g_down + (size_t)p0 * DIMX) + 2 * tid;
    const __half2* d1 = (const __half2*)(g_down + (size_t)p1 * DIMX) + 2 * tid;
    float4 a = x4[tid];
    float2 u0 = __half22float2(d0[0]), u1 = __half22float2(d0[1]);
    float2 v0 = __half22float2(d1[0]), v1 = __half22float2(d1[1]);
    float4 o;
    o.x = a.x + w0 * u0.x + w1 * v0.x;
    o.y = a.y + w0 * u0.y + w1 * v0.y;
    o.z = a.z + w0 * u1.x + w1 * v1.x;
    o.w = a.w + w0 * u1.y + w1 * v1.y;
    ((float4*)(out + (size_t)t * DIMX))[tid] = o;
}

// ---------------- launch ----------------
extern "C" void kernel_launch(void* const* d_in, const int* in_sizes, int n_in,
                              void* d_out, int out_size) {
    const float* x     = (const float*)d_in[0];
    const float* scale = (const float*)d_in[1];
    const float* wr    = (const float*)d_in[2];
    const float* wu    = (const float*)d_in[3];
    const float* wd    = (const float*)d_in[4];
    float* out = (float*)d_out;

    cudaFuncSetAttribute(k_up,   cudaFuncAttributeMaxDynamicSharedMemorySize, SMEM_TOT);
    cudaFuncSetAttribute(k_down, cudaFuncAttributeMaxDynamicSharedMemorySize, SMEM_TOT);

    k_prep<<<2048, 256>>>(wu, wd);
    k_rms_router<<<M_TOK, 256>>>(x, scale, wr);
    // grid: x = n-tile (fast: a wave shares A row-tile, keeps B in L2), y = row-tile (264 >= 263 worst case)
    k_up  <<<dim3(HID / 64, 264), 256, SMEM_TOT>>>();    // (32, 264)
    k_down<<<dim3(DIMX / BN, 264), 256, SMEM_TOT>>>();   // (8, 264)
    k_combine<<<M_TOK, 256>>>(x, out);
}